// round 5
// baseline (speedup 1.0000x reference)
#include <cuda_runtime.h>

// Graph_Learn: S[n,i,j] = exp(relu(sum_f |xm[n,i,f]-xm[n,j,f]|*a[f])) / colsum_i
// N=8, T=8 (slice t=4), V=512, F=64. Output (8,512,512) fp32.
// Three-phase: zero colsum -> symmetric tile scores (exp to d_out, colsum via
// atomics) -> streaming scale.

#define NB   8
#define TB   8
#define VB   512
#define FB   64
#define TS   64
#define NT   (VB / TS)
#define NPAIR (NT * (NT + 1) / 2)   // 36

typedef unsigned long long ull;

__device__ float g_colsum[NB * VB];   // scratch: per-(n,j) column sums

__device__ __forceinline__ ull addx2(ull a, ull b) {
    ull r; asm("add.rn.f32x2 %0, %1, %2;" : "=l"(r) : "l"(a), "l"(b)); return r;
}
__device__ __forceinline__ ull fmax2k(ull a, ull b, ull c) {
    ull r; asm("fma.rn.f32x2 %0, %1, %2, %3;" : "=l"(r) : "l"(a), "l"(b), "l"(c)); return r;
}
__device__ __forceinline__ ull packf2(float lo, float hi) {
    ull r; asm("mov.b64 %0, {%1, %2};" : "=l"(r) : "f"(lo), "f"(hi)); return r;
}
__device__ __forceinline__ float sum2(ull a) {
    float lo, hi; asm("mov.b64 {%0, %1}, %2;" : "=f"(lo), "=f"(hi) : "l"(a)); return lo + hi;
}

__global__ void zero_kernel() {
    g_colsum[blockIdx.x * 512 + threadIdx.x] = 0.f;
}

// smem (floats): xi[64][64] | xj[64][64] | ev[64][65] | sa[64] | ps[4][64]
#define SMA_XJ  (TS * FB)
#define SMA_EV  (2 * TS * FB)
#define SMA_A   (SMA_EV + TS * 65)
#define SMA_PS  (SMA_A + FB)
#define SMA_FLOATS (SMA_PS + 4 * TS)

__global__ __launch_bounds__(256, 2)
void score_kernel(const float* __restrict__ x,
                  const float* __restrict__ a,
                  float* __restrict__ out) {
    extern __shared__ float sm[];
    float* xi = sm;                 // [64][64]
    float* xj = sm + SMA_XJ;        // [64][64]
    float* ev = sm + SMA_EV;        // [64][65] padded
    float* sa = sm + SMA_A;         // [64]
    float* ps = sm + SMA_PS;        // [4][64]

    const int n   = blockIdx.y;
    const int tid = threadIdx.x;

    // decode upper-tri tile pair (ti <= tj)
    int ti = 0, rem = blockIdx.x;
    while (rem >= NT - ti) { rem -= NT - ti; ti++; }
    const int tj = ti + rem;

    const float* xbase = x + ((size_t)n * TB + TB / 2) * VB * FB;
    {
        const float4* si = (const float4*)(xbase + ti * TS * FB);
        const float4* sj = (const float4*)(xbase + tj * TS * FB);
        float4* xi4 = (float4*)xi;
        float4* xj4 = (float4*)xj;
        for (int k = tid; k < TS * FB / 4; k += 256) { xi4[k] = si[k]; xj4[k] = sj[k]; }
        if (tid < FB / 4) ((float4*)sa)[tid] = ((const float4*)a)[tid];
    }
    __syncthreads();

    const int jl = tid & (TS - 1);   // j within tile (0..63)
    const int ig = tid >> 6;         // i-group (0..3)

    // -xj row packed into registers (32 ull)
    ull xjn[FB / 2];
    {
        const float* jr = xj + jl * FB;
        #pragma unroll
        for (int k = 0; k < FB / 2; k++) xjn[k] = packf2(-jr[2*k], -jr[2*k+1]);
    }

    const ull ABSM = 0x7FFFFFFF7FFFFFFFULL;
    const ulonglong2* sa2 = (const ulonglong2*)sa;
    float* o = out + (size_t)n * VB * VB;
    float csum = 0.f;

    // mainloop: 2 i-rows per iter, 4 packed accumulator chains.
    // Direct tile written straight from registers (coalesced over jl).
    #pragma unroll 1
    for (int it = 0; it < TS / 8; it++) {        // 8 iters
        const int i0 = (it * 4 + ig) * 2;        // warp-uniform
        const int i1 = i0 + 1;
        const ulonglong2* r0 = (const ulonglong2*)(xi + i0 * FB);
        const ulonglong2* r1 = (const ulonglong2*)(xi + i1 * FB);
        ull a00 = 0, a01 = 0, a10 = 0, a11 = 0;
        #pragma unroll
        for (int k = 0; k < FB / 4; k++) {
            ulonglong2 av = sa2[k];
            ulonglong2 v0 = r0[k];
            ulonglong2 v1 = r1[k];
            ull d;
            d = addx2(v0.x, xjn[2*k])   & ABSM; a00 = fmax2k(d, av.x, a00);
            d = addx2(v0.y, xjn[2*k+1]) & ABSM; a01 = fmax2k(d, av.y, a01);
            d = addx2(v1.x, xjn[2*k])   & ABSM; a10 = fmax2k(d, av.x, a10);
            d = addx2(v1.y, xjn[2*k+1]) & ABSM; a11 = fmax2k(d, av.y, a11);
        }
        float s0 = sum2(a00) + sum2(a01);
        float s1 = sum2(a10) + sum2(a11);
        float e0 = __expf(fmaxf(s0, 0.f));
        float e1 = __expf(fmaxf(s1, 0.f));
        ev[i0 * 65 + jl] = e0;
        ev[i1 * 65 + jl] = e1;
        o[(size_t)(ti * TS + i0) * VB + tj * TS + jl] = e0;
        o[(size_t)(ti * TS + i1) * VB + tj * TS + jl] = e1;
        csum += e0 + e1;
    }

    // direct colsum: columns tj*64+jl, rows in ti-range
    ps[ig * TS + jl] = csum;
    __syncthreads();
    if (tid < TS) {
        float t = ps[tid] + ps[TS + tid] + ps[2 * TS + tid] + ps[3 * TS + tid];
        atomicAdd(&g_colsum[n * VB + tj * TS + tid], t);
    }

    if (ti != tj) {
        // transposed tile write: out[tj*64+jr][ti*64+il], coalesced over il
        const int il = tid & (TS - 1);
        const int jg = tid >> 6;
        float rsum = 0.f;
        #pragma unroll 1
        for (int m = 0; m < TS / 4; m++) {
            int jr = m * 4 + jg;
            float v = ev[il * 65 + jr];     // stride-65: conflict-free
            o[(size_t)(tj * TS + jr) * VB + ti * TS + il] = v;
            rsum += v;
        }
        // transposed colsum: columns ti*64+il, rows in tj-range
        __syncthreads();
        ps[jg * TS + il] = rsum;
        __syncthreads();
        if (tid < TS) {
            float t = ps[tid] + ps[TS + tid] + ps[2 * TS + tid] + ps[3 * TS + tid];
            atomicAdd(&g_colsum[n * VB + ti * TS + tid], t);
        }
    }
}

// Phase C: out[n][i][j] *= 1 / colsum[n][j].  Streaming, L2-resident.
__global__ __launch_bounds__(512, 2)
void scale_kernel(float* __restrict__ out) {
    const int n  = blockIdx.y;
    const int ic = blockIdx.x;           // 32-row chunk
    const int j4 = threadIdx.x & 127;    // float4 index over 512 j
    const int ir = threadIdx.x >> 7;     // 0..3

    float4 cs = ((const float4*)(g_colsum + n * VB))[j4];
    float4 inv;
    inv.x = 1.0f / cs.x; inv.y = 1.0f / cs.y;
    inv.z = 1.0f / cs.z; inv.w = 1.0f / cs.w;

    float4* o = (float4*)(out + (size_t)n * VB * VB) + j4;
    #pragma unroll
    for (int m = 0; m < 8; m++) {
        const size_t row = (size_t)(ic * 32 + m * 4 + ir) * (VB / 4);
        float4 v = o[row];
        v.x *= inv.x; v.y *= inv.y; v.z *= inv.z; v.w *= inv.w;
        o[row] = v;
    }
}

extern "C" void kernel_launch(void* const* d_in, const int* in_sizes, int n_in,
                              void* d_out, int out_size) {
    const float* x = (const float*)d_in[0];   // (8,8,512,64) fp32
    const float* a = (const float*)d_in[1];   // (64,1) fp32
    float* out = (float*)d_out;               // (8,512,512) fp32

    const int smem_bytes = SMA_FLOATS * (int)sizeof(float);  // ~50.7 KB
    cudaFuncSetAttribute(score_kernel,
                         cudaFuncAttributeMaxDynamicSharedMemorySize, smem_bytes);

    zero_kernel<<<NB, VB>>>();                 // zero g_colsum (4096 floats)

    dim3 gridA(NPAIR, NB);                     // (36, 8) = 288 blocks
    score_kernel<<<gridA, 256, smem_bytes>>>(x, a, out);

    dim3 gridC(VB / 32, NB);                   // (16, 8) = 128 blocks
    scale_kernel<<<gridC, 512>>>(out);
}

// round 8
// speedup vs baseline: 1.0209x; 1.0209x over previous
#include <cuda_runtime.h>

// Graph_Learn: S[n,i,j] = exp(relu(sum_f |xm[n,i,f]-xm[n,j,f]|*a[f])) / colsum_i
// N=8, T=8 (slice t=4), V=512, F=64. Output (8,512,512) fp32.
// Two-phase, deadlock-free: (A) symmetric tile scores -> unnormalized exp to
// d_out + disjoint-slot column partials (no atomics, no zeroing);
// (B) per-column inverse from partials -> streaming scale of d_out.

#define NB    8
#define TB    8
#define VB    512
#define FB    64
#define TS    64
#define NT    (VB / TS)                 // 8
#define NPAIR (NT * (NT + 1) / 2)       // 36

typedef unsigned long long ull;

__device__ float g_partial[NB * NT * VB];   // [n][d][col]; every slot written each call

__device__ __forceinline__ ull addx2(ull a, ull b) {
    ull r; asm("add.rn.f32x2 %0, %1, %2;" : "=l"(r) : "l"(a), "l"(b)); return r;
}
__device__ __forceinline__ ull fmax2k(ull a, ull b, ull c) {
    ull r; asm("fma.rn.f32x2 %0, %1, %2, %3;" : "=l"(r) : "l"(a), "l"(b), "l"(c)); return r;
}
__device__ __forceinline__ ull packf2(float lo, float hi) {
    ull r; asm("mov.b64 %0, {%1, %2};" : "=l"(r) : "f"(lo), "f"(hi)); return r;
}
__device__ __forceinline__ float sum2(ull a) {
    float lo, hi; asm("mov.b64 {%0, %1}, %2;" : "=f"(lo), "=f"(hi) : "l"(a)); return lo + hi;
}

// smem (floats): xi[64][64] | xj[64][64] | ev[64][65] | sa[64] | ps[4][64]
#define SMA_XJ   (TS * FB)
#define SMA_EV   (2 * TS * FB)
#define SMA_A    (SMA_EV + TS * 65)
#define SMA_PS   (SMA_A + FB)
#define SMA_FLOATS (SMA_PS + 4 * TS)

__global__ __launch_bounds__(256, 2)
void score_kernel(const float* __restrict__ x,
                  const float* __restrict__ a,
                  float* __restrict__ out) {
    extern __shared__ float sm[];
    float* xi = sm;                 // [64][64]
    float* xj = sm + SMA_XJ;        // [64][64]
    float* ev = sm + SMA_EV;        // [64][65] padded
    float* sa = sm + SMA_A;         // [64]
    float* ps = sm + SMA_PS;        // [4][64]

    const int n   = blockIdx.y;
    const int tid = threadIdx.x;

    // decode upper-tri tile pair (ti <= tj)
    int ti = 0, rem = blockIdx.x;
    while (rem >= NT - ti) { rem -= NT - ti; ti++; }
    const int tj = ti + rem;

    const float* xbase = x + ((size_t)n * TB + TB / 2) * VB * FB;
    {
        const float4* si = (const float4*)(xbase + ti * TS * FB);
        const float4* sj = (const float4*)(xbase + tj * TS * FB);
        float4* xi4 = (float4*)xi;
        float4* xj4 = (float4*)xj;
        for (int k = tid; k < TS * FB / 4; k += 256) { xi4[k] = si[k]; xj4[k] = sj[k]; }
        if (tid < FB / 4) ((float4*)sa)[tid] = ((const float4*)a)[tid];
    }
    __syncthreads();

    const int jl = tid & (TS - 1);   // j within tile (0..63)
    const int ig = tid >> 6;         // i-group (0..3)

    // -xj row packed into registers (32 ull)
    ull xjn[FB / 2];
    {
        const float* jr = xj + jl * FB;
        #pragma unroll
        for (int k = 0; k < FB / 2; k++) xjn[k] = packf2(-jr[2*k], -jr[2*k+1]);
    }

    const ull ABSM = 0x7FFFFFFF7FFFFFFFULL;
    const ulonglong2* sa2 = (const ulonglong2*)sa;
    float* o = out + (size_t)n * VB * VB;
    float csum = 0.f;

    // mainloop: 2 i-rows per iter, 4 packed accumulator chains.
    // Direct tile written straight from registers (coalesced over jl).
    #pragma unroll 1
    for (int it = 0; it < TS / 8; it++) {        // 8 iters
        const int i0 = (it * 4 + ig) * 2;        // warp-uniform
        const int i1 = i0 + 1;
        const ulonglong2* r0 = (const ulonglong2*)(xi + i0 * FB);
        const ulonglong2* r1 = (const ulonglong2*)(xi + i1 * FB);
        ull a00 = 0, a01 = 0, a10 = 0, a11 = 0;
        #pragma unroll
        for (int k = 0; k < FB / 4; k++) {
            ulonglong2 av = sa2[k];
            ulonglong2 v0 = r0[k];
            ulonglong2 v1 = r1[k];
            ull d;
            d = addx2(v0.x, xjn[2*k])   & ABSM; a00 = fmax2k(d, av.x, a00);
            d = addx2(v0.y, xjn[2*k+1]) & ABSM; a01 = fmax2k(d, av.y, a01);
            d = addx2(v1.x, xjn[2*k])   & ABSM; a10 = fmax2k(d, av.x, a10);
            d = addx2(v1.y, xjn[2*k+1]) & ABSM; a11 = fmax2k(d, av.y, a11);
        }
        float s0 = sum2(a00) + sum2(a01);
        float s1 = sum2(a10) + sum2(a11);
        float e0 = __expf(fmaxf(s0, 0.f));
        float e1 = __expf(fmaxf(s1, 0.f));
        ev[i0 * 65 + jl] = e0;
        ev[i1 * 65 + jl] = e1;
        o[(size_t)(ti * TS + i0) * VB + tj * TS + jl] = e0;
        o[(size_t)(ti * TS + i1) * VB + tj * TS + jl] = e1;
        csum += e0 + e1;
    }

    // direct partial: rows ti-range, columns tj*64+jl -> slot [n][ti][tj*64..]
    ps[ig * TS + jl] = csum;
    __syncthreads();
    if (tid < TS) {
        float t = ps[tid] + ps[TS + tid] + ps[2 * TS + tid] + ps[3 * TS + tid];
        g_partial[(n * NT + ti) * VB + tj * TS + tid] = t;
    }

    if (ti != tj) {
        // transposed tile write + row sums -> slot [n][tj][ti*64..]
        const int il = tid & (TS - 1);
        const int jg = tid >> 6;
        float rsum = 0.f;
        #pragma unroll 1
        for (int m = 0; m < TS / 4; m++) {
            int jr = m * 4 + jg;
            float v = ev[il * 65 + jr];     // stride-65: conflict-free
            o[(size_t)(tj * TS + jr) * VB + ti * TS + il] = v;
            rsum += v;
        }
        __syncthreads();                    // ps readers done before reuse
        ps[jg * TS + il] = rsum;
        __syncthreads();
        if (tid < TS) {
            float t = ps[tid] + ps[TS + tid] + ps[2 * TS + tid] + ps[3 * TS + tid];
            g_partial[(n * NT + tj) * VB + ti * TS + tid] = t;
        }
    }
}

// Phase B: inv[j] = 1/sum_d partial[n][d][j]; out[n][i][j] *= inv[j].
__global__ __launch_bounds__(512, 2)
void scale_kernel(float* __restrict__ out) {
    __shared__ float sinv[VB];
    const int n   = blockIdx.y;
    const int ic  = blockIdx.x;          // 32-row chunk
    const int tid = threadIdx.x;

    // per-column inverse (512 threads = 512 columns; 8 L2-hit loads each)
    {
        const float* p = g_partial + n * NT * VB + tid;
        float s = 0.f;
        #pragma unroll
        for (int d = 0; d < NT; d++) s += p[d * VB];
        sinv[tid] = 1.0f / s;
    }
    __syncthreads();

    const int j4 = tid & 127;            // float4 index over 512 j
    const int ir = tid >> 7;             // 0..3
    float4 inv = ((const float4*)sinv)[j4];
    float4* o = (float4*)(out + (size_t)n * VB * VB) + j4;
    #pragma unroll
    for (int m = 0; m < 8; m++) {
        const size_t row = (size_t)(ic * 32 + m * 4 + ir) * (VB / 4);
        float4 v = o[row];
        v.x *= inv.x; v.y *= inv.y; v.z *= inv.z; v.w *= inv.w;
        o[row] = v;
    }
}

extern "C" void kernel_launch(void* const* d_in, const int* in_sizes, int n_in,
                              void* d_out, int out_size) {
    const float* x = (const float*)d_in[0];   // (8,8,512,64) fp32
    const float* a = (const float*)d_in[1];   // (64,1) fp32
    float* out = (float*)d_out;               // (8,512,512) fp32

    const int smem_bytes = SMA_FLOATS * (int)sizeof(float);  // ~50.7 KB
    cudaFuncSetAttribute(score_kernel,
                         cudaFuncAttributeMaxDynamicSharedMemorySize, smem_bytes);

    dim3 gridA(NPAIR, NB);     // (36, 8) = 288 blocks
    score_kernel<<<gridA, 256, smem_bytes>>>(x, a, out);

    dim3 gridB(VB / 32, NB);   // (16, 8) = 128 blocks
    scale_kernel<<<gridB, 512>>>(out);
}

// round 9
// speedup vs baseline: 1.0815x; 1.0594x over previous
#include <cuda_runtime.h>

// Graph_Learn: S[n,i,j] = exp(relu(sum_f |xm[n,i,f]-xm[n,j,f]|*a[f])) / colsum_i
// N=8, T=8 (slice t=4), V=512, F=64. Output (8,512,512) fp32.
// Phase A: symmetric tile scores -> upper-tri unnormalized exp tiles in d_out
//          + disjoint-slot column partials (no atomics, no zeroing).
// Phase B: per tile-pair, load tile, build column inverses, write BOTH
//          normalized orientations (upper direct, lower transposed via smem).

#define NB    8
#define TB    8
#define VB    512
#define FB    64
#define TS    64
#define NT    (VB / TS)                 // 8
#define NPAIR (NT * (NT + 1) / 2)       // 36

typedef unsigned long long ull;

__device__ float g_partial[NB * NT * VB];   // [n][d][col]; every slot written each call

__device__ __forceinline__ ull addx2(ull a, ull b) {
    ull r; asm("add.rn.f32x2 %0, %1, %2;" : "=l"(r) : "l"(a), "l"(b)); return r;
}
__device__ __forceinline__ ull fmax2k(ull a, ull b, ull c) {
    ull r; asm("fma.rn.f32x2 %0, %1, %2, %3;" : "=l"(r) : "l"(a), "l"(b), "l"(c)); return r;
}
__device__ __forceinline__ ull packf2(float lo, float hi) {
    ull r; asm("mov.b64 %0, {%1, %2};" : "=l"(r) : "f"(lo), "f"(hi)); return r;
}
__device__ __forceinline__ float sum2(ull a) {
    float lo, hi; asm("mov.b64 {%0, %1}, %2;" : "=f"(lo), "=f"(hi) : "l"(a)); return lo + hi;
}

__device__ __forceinline__ void decode_pair(int bx, int& ti, int& tj) {
    int t = 0, rem = bx;
    while (rem >= NT - t) { rem -= NT - t; t++; }
    ti = t; tj = t + rem;
}

// ---------------- Phase A ----------------
// smem (floats): xi[64][64] | xj[64][64] | ev[64][65] | sa[64] | ps[4][64]
#define SMA_XJ   (TS * FB)
#define SMA_EV   (2 * TS * FB)
#define SMA_A    (SMA_EV + TS * 65)
#define SMA_PS   (SMA_A + FB)
#define SMA_FLOATS (SMA_PS + 4 * TS)

__global__ __launch_bounds__(256, 2)
void score_kernel(const float* __restrict__ x,
                  const float* __restrict__ a,
                  float* __restrict__ out) {
    extern __shared__ float sm[];
    float* xi = sm;                 // [64][64]
    float* xj = sm + SMA_XJ;        // [64][64]
    float* ev = sm + SMA_EV;        // [64][65] padded
    float* sa = sm + SMA_A;         // [64]
    float* ps = sm + SMA_PS;        // [4][64]

    const int n   = blockIdx.y;
    const int tid = threadIdx.x;
    int ti, tj; decode_pair(blockIdx.x, ti, tj);

    const float* xbase = x + ((size_t)n * TB + TB / 2) * VB * FB;
    {
        const float4* si = (const float4*)(xbase + ti * TS * FB);
        const float4* sj = (const float4*)(xbase + tj * TS * FB);
        float4* xi4 = (float4*)xi;
        float4* xj4 = (float4*)xj;
        for (int k = tid; k < TS * FB / 4; k += 256) { xi4[k] = si[k]; xj4[k] = sj[k]; }
        if (tid < FB / 4) ((float4*)sa)[tid] = ((const float4*)a)[tid];
    }
    __syncthreads();

    const int jl = tid & (TS - 1);   // j within tile (0..63)
    const int ig = tid >> 6;         // i-group (0..3)

    // -xj row packed into registers (32 ull)
    ull xjn[FB / 2];
    {
        const float* jr = xj + jl * FB;
        #pragma unroll
        for (int k = 0; k < FB / 2; k++) xjn[k] = packf2(-jr[2*k], -jr[2*k+1]);
    }

    const ull ABSM = 0x7FFFFFFF7FFFFFFFULL;
    const ulonglong2* sa2 = (const ulonglong2*)sa;
    float* o = out + (size_t)n * VB * VB;
    float csum = 0.f;

    // mainloop: 2 i-rows per iter, 4 packed accumulator chains.
    // Direct (upper-tri) tile written straight from registers.
    #pragma unroll 1
    for (int it = 0; it < TS / 8; it++) {        // 8 iters
        const int i0 = (it * 4 + ig) * 2;        // warp-uniform
        const int i1 = i0 + 1;
        const ulonglong2* r0 = (const ulonglong2*)(xi + i0 * FB);
        const ulonglong2* r1 = (const ulonglong2*)(xi + i1 * FB);
        ull a00 = 0, a01 = 0, a10 = 0, a11 = 0;
        #pragma unroll
        for (int k = 0; k < FB / 4; k++) {
            ulonglong2 av = sa2[k];
            ulonglong2 v0 = r0[k];
            ulonglong2 v1 = r1[k];
            ull d;
            d = addx2(v0.x, xjn[2*k])   & ABSM; a00 = fmax2k(d, av.x, a00);
            d = addx2(v0.y, xjn[2*k+1]) & ABSM; a01 = fmax2k(d, av.y, a01);
            d = addx2(v1.x, xjn[2*k])   & ABSM; a10 = fmax2k(d, av.x, a10);
            d = addx2(v1.y, xjn[2*k+1]) & ABSM; a11 = fmax2k(d, av.y, a11);
        }
        float s0 = sum2(a00) + sum2(a01);
        float s1 = sum2(a10) + sum2(a11);
        float e0 = __expf(fmaxf(s0, 0.f));
        float e1 = __expf(fmaxf(s1, 0.f));
        ev[i0 * 65 + jl] = e0;
        ev[i1 * 65 + jl] = e1;
        o[(size_t)(ti * TS + i0) * VB + tj * TS + jl] = e0;
        o[(size_t)(ti * TS + i1) * VB + tj * TS + jl] = e1;
        csum += e0 + e1;
    }

    // direct partial: rows ti-range, cols tj*64+jl -> slot [n][ti][tj*64..]
    ps[ig * TS + jl] = csum;
    __syncthreads();
    if (tid < TS) {
        float t = ps[tid] + ps[TS + tid] + ps[2 * TS + tid] + ps[3 * TS + tid];
        g_partial[(n * NT + ti) * VB + tj * TS + tid] = t;
    }

    if (ti != tj) {
        // transposed partial only (no gmem write): rows tj-range, cols ti*64+il
        const int il = tid & (TS - 1);
        const int jg = tid >> 6;
        float rsum = 0.f;
        #pragma unroll
        for (int m = 0; m < TS / 4; m++) {
            rsum += ev[il * 65 + (m * 4 + jg)];   // stride-65: conflict-free
        }
        __syncthreads();                          // ps readers done before reuse
        ps[jg * TS + il] = rsum;
        __syncthreads();
        if (tid < TS) {
            float t = ps[tid] + ps[TS + tid] + ps[2 * TS + tid] + ps[3 * TS + tid];
            g_partial[(n * NT + tj) * VB + ti * TS + tid] = t;
        }
    }
}

// ---------------- Phase B ----------------
// Per tile-pair: load upper tile, build invj/invi, write both orientations.
__global__ __launch_bounds__(512, 2)
void norm_kernel(float* __restrict__ out) {
    __shared__ float ev[TS * 65];
    __shared__ float invj[TS];
    __shared__ float invi[TS];

    const int n   = blockIdx.y;
    const int tid = threadIdx.x;
    int ti, tj; decode_pair(blockIdx.x, ti, tj);

    float* o = out + (size_t)n * VB * VB;
    const float* src = o + (size_t)(ti * TS) * VB + tj * TS;

    // load 64x64 tile into smem (stride-65), 2 float4 per thread
    #pragma unroll
    for (int q = 0; q < 2; q++) {
        int idx = q * 512 + tid;        // 0..1023 float4s
        int row = idx >> 4;             // /16
        int c4  = idx & 15;
        float4 v = ((const float4*)(src + (size_t)row * VB))[c4];
        float* dst = ev + row * 65 + c4 * 4;
        dst[0] = v.x; dst[1] = v.y; dst[2] = v.z; dst[3] = v.w;
    }

    // column inverses from partials (8 L2 loads per column)
    if (tid < TS) {
        const float* p = g_partial + n * NT * VB + tj * TS + tid;
        float s = 0.f;
        #pragma unroll
        for (int d = 0; d < NT; d++) s += p[d * VB];
        invj[tid] = 1.0f / s;
    } else if (tid < 2 * TS) {
        const float* p = g_partial + n * NT * VB + ti * TS + (tid - TS);
        float s = 0.f;
        #pragma unroll
        for (int d = 0; d < NT; d++) s += p[d * VB];
        invi[tid - TS] = 1.0f / s;
    }
    __syncthreads();

    const int jl = tid & (TS - 1);
    const int ig = tid >> 6;            // 0..7

    // direct (upper) normalized write — overwrites exactly what we read
    {
        const float fj = invj[jl];
        #pragma unroll
        for (int m = 0; m < TS / 8; m++) {
            int ir = m * 8 + ig;
            o[(size_t)(ti * TS + ir) * VB + tj * TS + jl] = ev[ir * 65 + jl] * fj;
        }
    }
    // transposed (lower) normalized write — strictly lower-tri, no block reads it
    if (ti != tj) {
        const float fi = invi[jl];      // column ti*64+jl of output
        #pragma unroll
        for (int m = 0; m < TS / 8; m++) {
            int jr = m * 8 + ig;
            o[(size_t)(tj * TS + jr) * VB + ti * TS + jl] = ev[jl * 65 + jr] * fi;
        }
    }
}

extern "C" void kernel_launch(void* const* d_in, const int* in_sizes, int n_in,
                              void* d_out, int out_size) {
    const float* x = (const float*)d_in[0];   // (8,8,512,64) fp32
    const float* a = (const float*)d_in[1];   // (64,1) fp32
    float* out = (float*)d_out;               // (8,512,512) fp32

    const int smem_bytes = SMA_FLOATS * (int)sizeof(float);  // ~50.7 KB
    cudaFuncSetAttribute(score_kernel,
                         cudaFuncAttributeMaxDynamicSharedMemorySize, smem_bytes);

    dim3 grid(NPAIR, NB);   // (36, 8) = 288 blocks for both phases
    score_kernel<<<grid, 256, smem_bytes>>>(x, a, out);
    norm_kernel<<<grid, 512>>>(out);
}

// round 10
// speedup vs baseline: 1.1218x; 1.0372x over previous
#include <cuda_runtime.h>

// Graph_Learn: S[n,i,j] = exp(relu(sum_f |xm[n,i,f]-xm[n,j,f]|*a[f])) / colsum_i
// N=8, T=8 (slice t=4), V=512, F=64. Output (8,512,512) fp32.
// Single persistent kernel launched COOPERATIVELY (driver-guaranteed
// co-residency of all 288 CTAs -> spin barrier cannot deadlock; if residency
// were impossible the launch errors out instead of hanging).
// Flow: symmetric tile scores -> per-block column partials (disjoint slots,
// no atomics) -> software grid barrier -> normalized writes from smem.

#define NB    8
#define TB    8
#define VB    512
#define FB    64
#define TS    64
#define NT    (VB / TS)                 // 8
#define NPAIR (NT * (NT + 1) / 2)       // 36
#define NBLK  (NPAIR * NB)              // 288 (<= 148 SMs * 2 CTA/SM = 296)

typedef unsigned long long ull;

__device__ float g_partial[NB * NT * VB];   // [n][d][col], each slot written once
__device__ ull   g_bar = 0ull;              // monotone generation counter

__device__ __forceinline__ ull addx2(ull a, ull b) {
    ull r; asm("add.rn.f32x2 %0, %1, %2;" : "=l"(r) : "l"(a), "l"(b)); return r;
}
__device__ __forceinline__ ull fmax2k(ull a, ull b, ull c) {
    ull r; asm("fma.rn.f32x2 %0, %1, %2, %3;" : "=l"(r) : "l"(a), "l"(b), "l"(c)); return r;
}
__device__ __forceinline__ ull packf2(float lo, float hi) {
    ull r; asm("mov.b64 %0, {%1, %2};" : "=l"(r) : "f"(lo), "f"(hi)); return r;
}
__device__ __forceinline__ float sum2(ull a) {
    float lo, hi; asm("mov.b64 {%0, %1}, %2;" : "=f"(lo), "=f"(hi) : "l"(a)); return lo + hi;
}

// smem (floats): xi[64][64] | xj[64][64] | ev[64][65] | sa[64] | ps[4][64] | invj[64] | invi[64]
#define SMA_XJ   (TS * FB)
#define SMA_EV   (2 * TS * FB)
#define SMA_A    (SMA_EV + TS * 65)
#define SMA_PS   (SMA_A + FB)
#define SMA_IJ   (SMA_PS + 4 * TS)
#define SMA_II   (SMA_IJ + TS)
#define SMA_FLOATS (SMA_II + TS)

__global__ __launch_bounds__(256, 2)
void graph_learn_fused(const float* __restrict__ x,
                       const float* __restrict__ a,
                       float* __restrict__ out) {
    extern __shared__ float sm[];
    float* xi   = sm;                 // [64][64]
    float* xj   = sm + SMA_XJ;        // [64][64]
    float* ev   = sm + SMA_EV;        // [64][65] padded
    float* sa   = sm + SMA_A;         // [64]
    float* ps   = sm + SMA_PS;        // [4][64]
    float* invj = sm + SMA_IJ;        // [64]
    float* invi = sm + SMA_II;        // [64]

    const int n   = blockIdx.y;
    const int tid = threadIdx.x;

    // decode upper-tri tile pair (ti <= tj)
    int ti = 0, rem = blockIdx.x;
    while (rem >= NT - ti) { rem -= NT - ti; ti++; }
    const int tj = ti + rem;

    const float* xbase = x + ((size_t)n * TB + TB / 2) * VB * FB;
    {
        const float4* si = (const float4*)(xbase + ti * TS * FB);
        const float4* sj = (const float4*)(xbase + tj * TS * FB);
        float4* xi4 = (float4*)xi;
        float4* xj4 = (float4*)xj;
        for (int k = tid; k < TS * FB / 4; k += 256) { xi4[k] = si[k]; xj4[k] = sj[k]; }
        if (tid < FB / 4) ((float4*)sa)[tid] = ((const float4*)a)[tid];
    }
    __syncthreads();

    const int jl = tid & (TS - 1);   // j within tile (0..63)
    const int ig = tid >> 6;         // i-group (0..3)

    // -xj row packed into registers (32 ull)
    ull xjn[FB / 2];
    {
        const float* jr = xj + jl * FB;
        #pragma unroll
        for (int k = 0; k < FB / 2; k++) xjn[k] = packf2(-jr[2*k], -jr[2*k+1]);
    }

    const ull ABSM = 0x7FFFFFFF7FFFFFFFULL;
    const ulonglong2* sa2 = (const ulonglong2*)sa;
    float csum = 0.f;

    // mainloop: 2 i-rows per iter, 4 packed accumulator chains; exp -> smem only
    #pragma unroll 1
    for (int it = 0; it < TS / 8; it++) {        // 8 iters
        const int i0 = (it * 4 + ig) * 2;        // warp-uniform
        const int i1 = i0 + 1;
        const ulonglong2* r0 = (const ulonglong2*)(xi + i0 * FB);
        const ulonglong2* r1 = (const ulonglong2*)(xi + i1 * FB);
        ull a00 = 0, a01 = 0, a10 = 0, a11 = 0;
        #pragma unroll
        for (int k = 0; k < FB / 4; k++) {
            ulonglong2 av = sa2[k];
            ulonglong2 v0 = r0[k];
            ulonglong2 v1 = r1[k];
            ull d;
            d = addx2(v0.x, xjn[2*k])   & ABSM; a00 = fmax2k(d, av.x, a00);
            d = addx2(v0.y, xjn[2*k+1]) & ABSM; a01 = fmax2k(d, av.y, a01);
            d = addx2(v1.x, xjn[2*k])   & ABSM; a10 = fmax2k(d, av.x, a10);
            d = addx2(v1.y, xjn[2*k+1]) & ABSM; a11 = fmax2k(d, av.y, a11);
        }
        float s0 = sum2(a00) + sum2(a01);
        float s1 = sum2(a10) + sum2(a11);
        float e0 = __expf(fmaxf(s0, 0.f));
        float e1 = __expf(fmaxf(s1, 0.f));
        ev[i0 * 65 + jl] = e0;
        ev[i1 * 65 + jl] = e1;
        csum += e0 + e1;
    }

    // direct partial: rows ti-range, columns tj*64+jl -> slot [n][ti]
    ps[ig * TS + jl] = csum;
    __syncthreads();
    if (tid < TS) {
        float t = ps[tid] + ps[TS + tid] + ps[2 * TS + tid] + ps[3 * TS + tid];
        g_partial[(n * NT + ti) * VB + tj * TS + tid] = t;
    }

    const int il = tid & (TS - 1);
    const int jg = tid >> 6;
    if (ti != tj) {
        // transposed partial: rows tj-range, columns ti*64+il -> slot [n][tj]
        float rsum = 0.f;
        #pragma unroll
        for (int m = 0; m < TS / 4; m++) {
            rsum += ev[il * 65 + (m * 4 + jg)];   // stride-65: conflict-free
        }
        __syncthreads();                          // ps readers done
        ps[jg * TS + il] = rsum;
        __syncthreads();
        if (tid < TS) {
            float t = ps[tid] + ps[TS + tid] + ps[2 * TS + tid] + ps[3 * TS + tid];
            g_partial[(n * NT + tj) * VB + ti * TS + tid] = t;
        }
    }

    // ---- software grid barrier (generation counting, replay-safe;
    //      co-residency guaranteed by cooperative launch) ----
    __threadfence();      // publish this thread's g_partial stores
    __syncthreads();      // all threads' fences done before representative arrives
    if (tid == 0) {
        ull my = atomicAdd(&g_bar, 1ull);
        ull target = (my / NBLK + 1ull) * (ull)NBLK;
        while (*((volatile ull*)&g_bar) < target) { __nanosleep(32); }
    }
    __syncthreads();
    __threadfence();      // acquire side: order subsequent g_partial reads

    // ---- column sums -> inverse norms ----
    if (tid < TS) {
        const float* p = g_partial + n * NT * VB + tj * TS + tid;
        float s = 0.f;
        #pragma unroll
        for (int d = 0; d < NT; d++) s += p[d * VB];
        invj[tid] = 1.0f / s;
    } else if (tid < 2 * TS && ti != tj) {
        const float* p = g_partial + n * NT * VB + ti * TS + (tid - TS);
        float s = 0.f;
        #pragma unroll
        for (int d = 0; d < NT; d++) s += p[d * VB];
        invi[tid - TS] = 1.0f / s;
    }
    __syncthreads();

    // ---- normalized writes (single gmem write per element) ----
    float* o = out + (size_t)n * VB * VB;
    {
        const float fj = invj[jl];
        #pragma unroll
        for (int m = 0; m < TS / 4; m++) {
            int ir = m * 4 + ig;
            o[(size_t)(ti * TS + ir) * VB + tj * TS + jl] = ev[ir * 65 + jl] * fj;
        }
    }
    if (ti != tj) {
        const float fi = invi[il];
        #pragma unroll
        for (int m = 0; m < TS / 4; m++) {
            int jr = m * 4 + jg;
            o[(size_t)(tj * TS + jr) * VB + ti * TS + il] = ev[il * 65 + jr] * fi;
        }
    }
}

extern "C" void kernel_launch(void* const* d_in, const int* in_sizes, int n_in,
                              void* d_out, int out_size) {
    const float* x = (const float*)d_in[0];   // (8,8,512,64) fp32
    const float* a = (const float*)d_in[1];   // (64,1) fp32
    float* out = (float*)d_out;               // (8,512,512) fp32

    const int smem_bytes = SMA_FLOATS * (int)sizeof(float);  // ~51.2 KB
    cudaFuncSetAttribute(graph_learn_fused,
                         cudaFuncAttributeMaxDynamicSharedMemorySize, smem_bytes);

    dim3 grid(NPAIR, NB);   // (36, 8) = 288 blocks, one co-resident wave
    dim3 block(256, 1, 1);
    void* args[] = { (void*)&x, (void*)&a, (void*)&out };
    // Cooperative launch: driver verifies all 288 CTAs can be co-resident
    // (fails with an error instead of deadlocking if not).
    cudaLaunchCooperativeKernel((void*)graph_learn_fused, grid, block,
                                args, (size_t)smem_bytes, (cudaStream_t)0);
}